// round 8
// baseline (speedup 1.0000x reference)
#include <cuda_runtime.h>

#define N_NODES 50000
#define N_EDGES 800000
#define DIM 128
#define HEADS 4
#define NEG_SLOPE 0.2f
#define LN_EPS 1e-5f

#define SCAN_BLK 256
#define N_SCAN_BLKS ((N_NODES + SCAN_BLK - 1) / SCAN_BLK)   // 196

// Scratch (device globals: no allocation allowed in kernel_launch)
__device__ __align__(16) float g_xl[N_NODES * DIM];   // 25.6 MB
__device__ __align__(16) float g_xr[N_NODES * DIM];   // 25.6 MB
__device__ int g_deg[N_NODES];
__device__ int g_off[N_NODES];
__device__ int g_cursor[N_NODES];
__device__ int g_bsum[N_SCAN_BLKS];
__device__ int g_csr_src[N_EDGES];
__device__ int g_is64;

__device__ __forceinline__ int load_idx(const void* raw, int pos, int is64) {
    return is64 ? (int)((const long long*)raw)[pos] : ((const int*)raw)[pos];
}

// f32x2 packed helpers (sm_103a FFMA2 — only reachable via PTX)
__device__ __forceinline__ unsigned long long pack_dup(float v) {
    unsigned long long r;
    asm("mov.b64 %0, {%1, %1};" : "=l"(r) : "f"(v));
    return r;
}
__device__ __forceinline__ void fma2(unsigned long long& acc,
                                     unsigned long long a, unsigned long long b) {
    asm("fma.rn.f32x2 %0, %1, %2, %0;" : "+l"(acc) : "l"(a), "l"(b));
}
__device__ __forceinline__ float2 unpack2(unsigned long long v) {
    float lo, hi;
    asm("mov.b64 {%0, %1}, %2;" : "=f"(lo), "=f"(hi) : "l"(v));
    return make_float2(lo, hi);
}

// ---------------------------------------------------------------------------
// launch 0: dtype sniff + zero degree array.
// ---------------------------------------------------------------------------
__global__ void prep_kernel(const void* __restrict__ ei_raw) {
    int i = blockIdx.x * blockDim.x + threadIdx.x;
    if (i == 0) {
        const long long* e64 = (const long long*)ei_raw;
        int ok = 1;
        #pragma unroll
        for (int j = 0; j < 16; j++) {
            long long v = e64[j];
            if (v < 0 || v >= N_NODES) ok = 0;
        }
        g_is64 = ok;
    }
    int stride = gridDim.x * blockDim.x;
    for (int j = i; j < N_NODES; j += stride) g_deg[j] = 0;
}

// launch 1: degree histogram
__global__ void hist_kernel(const void* __restrict__ ei_raw) {
    int is64 = g_is64;
    int i = blockIdx.x * blockDim.x + threadIdx.x;
    int stride = gridDim.x * blockDim.x;
    for (int e = i; e < N_EDGES; e += stride) {
        int d = load_idx(ei_raw, N_EDGES + e, is64);
        atomicAdd(&g_deg[d], 1);
    }
}

// launch 2: per-block inclusive scan of deg chunk; block total to g_bsum.
__global__ void scan1_kernel() {
    __shared__ int sh[SCAN_BLK];
    int tid = threadIdx.x;
    int i = blockIdx.x * SCAN_BLK + tid;
    int v = (i < N_NODES) ? g_deg[i] : 0;
    sh[tid] = v;
    __syncthreads();
    #pragma unroll
    for (int o = 1; o < SCAN_BLK; o <<= 1) {
        int t = (tid >= o) ? sh[tid - o] : 0;
        __syncthreads();
        sh[tid] += t;
        __syncthreads();
    }
    if (i < N_NODES) g_off[i] = sh[tid];           // inclusive local
    if (tid == SCAN_BLK - 1) g_bsum[blockIdx.x] = sh[tid];
}

// ---------------------------------------------------------------------------
// launch 3 (ncu captures this index): GEMM xl = x@W_l + b_l ; xr = x@W_r + b_r.
// Two warps share an 8-node tile; warp parity selects a 64-column half.
// Lane owns ONE f32x2 column pair (cols colbase+2L, +2L+1) of BOTH matrices:
// per k the warp loads only 2x LDG.64 of W for 8 nodes (64 B/node/k -> 410 MB
// total W traffic, 4x less than R7 whose profile showed L1 = 78.9%).
// 50000 = 6250 x 8 exactly: no node bounds checks.
// ---------------------------------------------------------------------------
__global__ void __launch_bounds__(256, 3)
gemm_kernel(const float* __restrict__ x,
            const float* __restrict__ Wl, const float* __restrict__ bl,
            const float* __restrict__ Wr, const float* __restrict__ br) {
    const int lane = threadIdx.x & 31;
    const int gw = (blockIdx.x * blockDim.x + threadIdx.x) >> 5;
    const int ngw = (gridDim.x * blockDim.x) >> 5;
    const int NPW = 8;
    const int NTILES2 = (N_NODES / NPW) * 2;   // 12500 (tile, half) pairs

    for (int w = gw; w < NTILES2; w += ngw) {
        const int base = (w >> 1) * NPW;
        const int col = (w & 1) * 64 + lane * 2;   // lane's column pair

        float2 bl2 = *(const float2*)(bl + col);
        float2 br2 = *(const float2*)(br + col);

        // x rows of the tile, distributed: lane L holds x[n][4L..4L+4)
        float4 xv[NPW];
        #pragma unroll
        for (int i = 0; i < NPW; i++)
            xv[i] = ((const float4*)(x + (size_t)(base + i) * DIM))[lane];

        unsigned long long al[NPW], ar[NPW];
        #pragma unroll
        for (int i = 0; i < NPW; i++) { al[i] = 0ull; ar[i] = 0ull; }

        #pragma unroll
        for (int k4 = 0; k4 < DIM / 4; k4++) {
            #pragma unroll
            for (int c = 0; c < 4; c++) {
                const int k = k4 * 4 + c;
                unsigned long long wl = *(const unsigned long long*)(Wl + (size_t)k * DIM + col);
                unsigned long long wr = *(const unsigned long long*)(Wr + (size_t)k * DIM + col);
                #pragma unroll
                for (int i = 0; i < NPW; i++) {
                    float comp = (c == 0) ? xv[i].x : (c == 1) ? xv[i].y
                               : (c == 2) ? xv[i].z : xv[i].w;
                    float xk = __shfl_sync(0xffffffffu, comp, k4);
                    unsigned long long xk2 = pack_dup(xk);
                    fma2(al[i], wl, xk2);
                    fma2(ar[i], wr, xk2);
                }
            }
        }

        #pragma unroll
        for (int i = 0; i < NPW; i++) {
            int n = base + i;
            float2 l = unpack2(al[i]);
            float2 r = unpack2(ar[i]);
            l.x += bl2.x; l.y += bl2.y;
            r.x += br2.x; r.y += br2.y;
            *(float2*)(g_xl + (size_t)n * DIM + col) = l;
            *(float2*)(g_xr + (size_t)n * DIM + col) = r;
        }
    }
}

// launch 4: finalize offsets. Each block recomputes its own exclusive prefix
// of the block totals (<= 196 values) with a shared-mem reduction.
__global__ void scan3_kernel() {
    __shared__ int sh[SCAN_BLK];
    int tid = threadIdx.x;
    int bid = blockIdx.x;
    sh[tid] = (tid < bid) ? g_bsum[tid] : 0;        // bid <= 196 <= SCAN_BLK
    __syncthreads();
    #pragma unroll
    for (int o = SCAN_BLK / 2; o > 0; o >>= 1) {
        if (tid < o) sh[tid] += sh[tid + o];
        __syncthreads();
    }
    int prefix = sh[0];
    int i = bid * SCAN_BLK + tid;
    if (i < N_NODES) {
        int excl = g_off[i] - g_deg[i] + prefix;
        g_off[i] = excl;
        g_cursor[i] = excl;
    }
}

// launch 5: CSR fill
__global__ void fill_kernel(const void* __restrict__ ei_raw) {
    int is64 = g_is64;
    int i = blockIdx.x * blockDim.x + threadIdx.x;
    int stride = gridDim.x * blockDim.x;
    for (int e = i; e < N_EDGES; e += stride) {
        int s = load_idx(ei_raw, e, is64);
        int d = load_idx(ei_raw, N_EDGES + e, is64);
        int pos = atomicAdd(&g_cursor[d], 1);
        g_csr_src[pos] = s;
    }
}

// ---------------------------------------------------------------------------
// launch 6: fused per-dst softmax-gather + residual + LN.
// One warp per destination node; edge loop unrolled x4 with independent
// accumulator pairs (MLP=4). alpha = exp(e)/sum(exp(e)) equals reference
// softmax (max cancels; +1e-16 negligible since max term contributes 1).
// ---------------------------------------------------------------------------
__device__ __forceinline__ float edge_logit(float4 a, float4 xr4, float4 at) {
    float vx = a.x + xr4.x; vx = vx > 0.f ? vx : NEG_SLOPE * vx;
    float vy = a.y + xr4.y; vy = vy > 0.f ? vy : NEG_SLOPE * vy;
    float vz = a.z + xr4.z; vz = vz > 0.f ? vz : NEG_SLOPE * vz;
    float vw = a.w + xr4.w; vw = vw > 0.f ? vw : NEG_SLOPE * vw;
    return vx * at.x + vy * at.y + vz * at.z + vw * at.w;
}

__global__ void fused_edge_kernel(const float* __restrict__ x,
                                  const float* __restrict__ att,
                                  const float* __restrict__ bias,
                                  const float* __restrict__ gamma,
                                  const float* __restrict__ beta,
                                  float* __restrict__ out) {
    const int lane = threadIdx.x & 31;
    const int warp = (blockIdx.x * blockDim.x + threadIdx.x) >> 5;
    const int nwarp = (gridDim.x * blockDim.x) >> 5;
    const unsigned FULL = 0xffffffffu;

    float4 at = ((const float4*)att)[lane];
    float4 bi = ((const float4*)bias)[lane];
    float4 ga = ((const float4*)gamma)[lane];
    float4 be = ((const float4*)beta)[lane];

    for (int d = warp; d < N_NODES; d += nwarp) {
        const int beg = g_off[d];
        const int deg = g_deg[d];
        float4 xr4 = ((const float4*)(g_xr + (size_t)d * DIM))[lane];

        float4 accA = make_float4(0.f, 0.f, 0.f, 0.f);
        float4 accB = make_float4(0.f, 0.f, 0.f, 0.f);
        float denA = 0.f, denB = 0.f;

        for (int base = 0; base < deg; base += 32) {
            int cnt = min(32, deg - base);
            int my_src = (lane < cnt) ? g_csr_src[beg + base + lane] : 0;

            int j = 0;
            for (; j + 4 <= cnt; j += 4) {
                int s0 = __shfl_sync(FULL, my_src, j + 0);
                int s1 = __shfl_sync(FULL, my_src, j + 1);
                int s2 = __shfl_sync(FULL, my_src, j + 2);
                int s3 = __shfl_sync(FULL, my_src, j + 3);
                float4 a0 = ((const float4*)(g_xl + (size_t)s0 * DIM))[lane];
                float4 a1 = ((const float4*)(g_xl + (size_t)s1 * DIM))[lane];
                float4 a2 = ((const float4*)(g_xl + (size_t)s2 * DIM))[lane];
                float4 a3 = ((const float4*)(g_xl + (size_t)s3 * DIM))[lane];

                float p0 = edge_logit(a0, xr4, at);
                float p1 = edge_logit(a1, xr4, at);
                float p2 = edge_logit(a2, xr4, at);
                float p3 = edge_logit(a3, xr4, at);
                #pragma unroll
                for (int off = 4; off > 0; off >>= 1) {
                    p0 += __shfl_xor_sync(FULL, p0, off);
                    p1 += __shfl_xor_sync(FULL, p1, off);
                    p2 += __shfl_xor_sync(FULL, p2, off);
                    p3 += __shfl_xor_sync(FULL, p3, off);
                }
                float w0 = __expf(p0), w1 = __expf(p1);
                float w2 = __expf(p2), w3 = __expf(p3);
                denA += w0 + w1;
                denB += w2 + w3;
                accA.x += w0 * a0.x + w1 * a1.x;
                accA.y += w0 * a0.y + w1 * a1.y;
                accA.z += w0 * a0.z + w1 * a1.z;
                accA.w += w0 * a0.w + w1 * a1.w;
                accB.x += w2 * a2.x + w3 * a3.x;
                accB.y += w2 * a2.y + w3 * a3.y;
                accB.z += w2 * a2.z + w3 * a3.z;
                accB.w += w2 * a2.w + w3 * a3.w;
            }
            for (; j < cnt; j++) {
                int s = __shfl_sync(FULL, my_src, j);
                float4 a = ((const float4*)(g_xl + (size_t)s * DIM))[lane];
                float p = edge_logit(a, xr4, at);
                #pragma unroll
                for (int off = 4; off > 0; off >>= 1)
                    p += __shfl_xor_sync(FULL, p, off);
                float w = __expf(p);
                denA += w;
                accA.x += w * a.x;
                accA.y += w * a.y;
                accA.z += w * a.z;
                accA.w += w * a.w;
            }
        }

        float den = denA + denB;
        float4 acc = make_float4(accA.x + accB.x, accA.y + accB.y,
                                 accA.z + accB.z, accA.w + accB.w);
        float inv = (den > 0.f) ? __frcp_rn(den) : 0.f;

        float4 xv = ((const float4*)(x + (size_t)d * DIM))[lane];
        float4 o;
        o.x = acc.x * inv + bi.x + xv.x;
        o.y = acc.y * inv + bi.y + xv.y;
        o.z = acc.z * inv + bi.z + xv.z;
        o.w = acc.w * inv + bi.w + xv.w;

        float s = o.x + o.y + o.z + o.w;
        #pragma unroll
        for (int off = 16; off > 0; off >>= 1)
            s += __shfl_xor_sync(FULL, s, off);
        float mu = s * (1.0f / DIM);

        float dx = o.x - mu, dy = o.y - mu, dz = o.z - mu, dw = o.w - mu;
        float q = dx * dx + dy * dy + dz * dz + dw * dw;
        #pragma unroll
        for (int off = 16; off > 0; off >>= 1)
            q += __shfl_xor_sync(FULL, q, off);
        float rs = rsqrtf(q * (1.0f / DIM) + LN_EPS);

        float4 r;
        r.x = dx * rs * ga.x + be.x;
        r.y = dy * rs * ga.y + be.y;
        r.z = dz * rs * ga.z + be.z;
        r.w = dw * rs * ga.w + be.w;
        ((float4*)(out + (size_t)d * DIM))[lane] = r;
    }
}

extern "C" void kernel_launch(void* const* d_in, const int* in_sizes, int n_in,
                              void* d_out, int out_size) {
    const float* x     = (const float*)d_in[0];
    const void*  ei    = d_in[1];
    const float* Wl    = (const float*)d_in[2];
    const float* bl    = (const float*)d_in[3];
    const float* Wr    = (const float*)d_in[4];
    const float* br    = (const float*)d_in[5];
    const float* att   = (const float*)d_in[6];
    const float* bias  = (const float*)d_in[7];
    const float* gamma = (const float*)d_in[8];
    const float* beta  = (const float*)d_in[9];
    float*       out   = (float*)d_out;

    prep_kernel<<<256, 256>>>(ei);                          // 0
    hist_kernel<<<1024, 256>>>(ei);                         // 1
    scan1_kernel<<<N_SCAN_BLKS, SCAN_BLK>>>();              // 2
    // 12500 (tile, col-half) warps / 8 warps per block = 1563 blocks
    gemm_kernel<<<1563, 256>>>(x, Wl, bl, Wr, br);          // 3  <- ncu captures
    scan3_kernel<<<N_SCAN_BLKS, SCAN_BLK>>>();              // 4
    fill_kernel<<<1024, 256>>>(ei);                         // 5
    fused_edge_kernel<<<6250, 256>>>(x, att, bias, gamma, beta, out);  // 6
}

// round 9
// speedup vs baseline: 1.1797x; 1.1797x over previous
#include <cuda_runtime.h>

#define N_NODES 50000
#define N_EDGES 800000
#define DIM 128
#define HEADS 4
#define NEG_SLOPE 0.2f
#define LN_EPS 1e-5f

#define SCAN_BLK 256
#define N_SCAN_BLKS ((N_NODES + SCAN_BLK - 1) / SCAN_BLK)   // 196

#define GEMM_TILE 64        // nodes per block
#define GEMM_SMEM (GEMM_TILE * DIM * 8)   // dup'd x tile, u64 each = 64 KB

// Scratch (device globals: no allocation allowed in kernel_launch)
__device__ __align__(16) float g_xl[N_NODES * DIM];   // 25.6 MB
__device__ __align__(16) float g_xr[N_NODES * DIM];   // 25.6 MB
__device__ int g_deg[N_NODES];
__device__ int g_off[N_NODES];
__device__ int g_cursor[N_NODES];
__device__ int g_bsum[N_SCAN_BLKS];
__device__ int g_csr_src[N_EDGES];
__device__ int g_is64;

__device__ __forceinline__ int load_idx(const void* raw, int pos, int is64) {
    return is64 ? (int)((const long long*)raw)[pos] : ((const int*)raw)[pos];
}

// f32x2 packed helpers (sm_103a FFMA2 — only reachable via PTX)
__device__ __forceinline__ unsigned long long pack_dup(float v) {
    unsigned long long r;
    asm("mov.b64 %0, {%1, %1};" : "=l"(r) : "f"(v));
    return r;
}
__device__ __forceinline__ void fma2(unsigned long long& acc,
                                     unsigned long long a, unsigned long long b) {
    asm("fma.rn.f32x2 %0, %1, %2, %0;" : "+l"(acc) : "l"(a), "l"(b));
}
__device__ __forceinline__ float2 unpack2(unsigned long long v) {
    float lo, hi;
    asm("mov.b64 {%0, %1}, %2;" : "=f"(lo), "=f"(hi) : "l"(v));
    return make_float2(lo, hi);
}

// ---------------------------------------------------------------------------
// launch 0: dtype sniff + zero degree array.
// ---------------------------------------------------------------------------
__global__ void prep_kernel(const void* __restrict__ ei_raw) {
    int i = blockIdx.x * blockDim.x + threadIdx.x;
    if (i == 0) {
        const long long* e64 = (const long long*)ei_raw;
        int ok = 1;
        #pragma unroll
        for (int j = 0; j < 16; j++) {
            long long v = e64[j];
            if (v < 0 || v >= N_NODES) ok = 0;
        }
        g_is64 = ok;
    }
    int stride = gridDim.x * blockDim.x;
    for (int j = i; j < N_NODES; j += stride) g_deg[j] = 0;
}

// launch 1: degree histogram
__global__ void hist_kernel(const void* __restrict__ ei_raw) {
    int is64 = g_is64;
    int i = blockIdx.x * blockDim.x + threadIdx.x;
    int stride = gridDim.x * blockDim.x;
    for (int e = i; e < N_EDGES; e += stride) {
        int d = load_idx(ei_raw, N_EDGES + e, is64);
        atomicAdd(&g_deg[d], 1);
    }
}

// launch 2: per-block inclusive scan of deg chunk; block total to g_bsum.
__global__ void scan1_kernel() {
    __shared__ int sh[SCAN_BLK];
    int tid = threadIdx.x;
    int i = blockIdx.x * SCAN_BLK + tid;
    int v = (i < N_NODES) ? g_deg[i] : 0;
    sh[tid] = v;
    __syncthreads();
    #pragma unroll
    for (int o = 1; o < SCAN_BLK; o <<= 1) {
        int t = (tid >= o) ? sh[tid - o] : 0;
        __syncthreads();
        sh[tid] += t;
        __syncthreads();
    }
    if (i < N_NODES) g_off[i] = sh[tid];           // inclusive local
    if (tid == SCAN_BLK - 1) g_bsum[blockIdx.x] = sh[tid];
}

// ---------------------------------------------------------------------------
// launch 3 (ncu captures this index): GEMM xl = x@W_l + b_l ; xr = x@W_r + b_r.
// Block tile = 64 nodes. x is pre-duplicated into dynamic smem as packed
// {v,v} u64 (the exact FFMA2 multiplier), so the inner loop is pure
// LDG(W row) + LDS.64 broadcast + FFMA2 — no SHFL, no MOV (R8 regression
// showed the shfl/pack broadcast machinery starving the fma pipe).
// Each warp computes 8 nodes x all 128 cols of BOTH matrices:
//   per k: 2x LDG.128 + 8x LDS.64 + 32x FFMA2 (76% fma mix).
// ---------------------------------------------------------------------------
__global__ void __launch_bounds__(256, 2)
gemm_kernel(const float* __restrict__ x,
            const float* __restrict__ Wl, const float* __restrict__ bl,
            const float* __restrict__ Wr, const float* __restrict__ br) {
    extern __shared__ unsigned long long sx[];   // [GEMM_TILE][DIM] dup'd
    const int tid = threadIdx.x;
    const int lane = tid & 31;
    const int wid = tid >> 5;
    const int base = blockIdx.x * GEMM_TILE;

    // cooperative load + dup: GEMM_TILE nodes x DIM dims, float4 granular
    for (int idx = tid; idx < GEMM_TILE * DIM / 4; idx += 256) {
        int off = idx * 4;                 // float offset within tile
        int node = off >> 7;               // /DIM
        int col = off & (DIM - 1);
        float4 v = make_float4(0.f, 0.f, 0.f, 0.f);
        if (base + node < N_NODES)
            v = *(const float4*)(x + (size_t)(base + node) * DIM + col);
        sx[off + 0] = pack_dup(v.x);
        sx[off + 1] = pack_dup(v.y);
        sx[off + 2] = pack_dup(v.z);
        sx[off + 3] = pack_dup(v.w);
    }
    __syncthreads();

    const int nbase = wid * 8;             // warp's local node base
    if (base + nbase < N_NODES) {
        const unsigned long long* sxw = sx + (size_t)nbase * DIM;

        unsigned long long al[8][2], ar[8][2];
        #pragma unroll
        for (int i = 0; i < 8; i++) {
            al[i][0] = 0ull; al[i][1] = 0ull;
            ar[i][0] = 0ull; ar[i][1] = 0ull;
        }

        #pragma unroll 4
        for (int k = 0; k < DIM; k++) {
            ulonglong2 wl = *(const ulonglong2*)(Wl + (size_t)k * DIM + lane * 4);
            ulonglong2 wr = *(const ulonglong2*)(Wr + (size_t)k * DIM + lane * 4);
            #pragma unroll
            for (int i = 0; i < 8; i++) {
                unsigned long long xk2 = sxw[i * DIM + k];   // LDS.64 broadcast
                fma2(al[i][0], wl.x, xk2);
                fma2(al[i][1], wl.y, xk2);
                fma2(ar[i][0], wr.x, xk2);
                fma2(ar[i][1], wr.y, xk2);
            }
        }

        float4 b_l = ((const float4*)bl)[lane];
        float4 b_r = ((const float4*)br)[lane];
        #pragma unroll
        for (int i = 0; i < 8; i++) {
            int n = base + nbase + i;
            if (n < N_NODES) {
                float2 l0 = unpack2(al[i][0]);
                float2 l1 = unpack2(al[i][1]);
                float2 r0 = unpack2(ar[i][0]);
                float2 r1 = unpack2(ar[i][1]);
                float4 ol = make_float4(l0.x + b_l.x, l0.y + b_l.y,
                                        l1.x + b_l.z, l1.y + b_l.w);
                float4 orr = make_float4(r0.x + b_r.x, r0.y + b_r.y,
                                         r1.x + b_r.z, r1.y + b_r.w);
                ((float4*)(g_xl + (size_t)n * DIM))[lane] = ol;
                ((float4*)(g_xr + (size_t)n * DIM))[lane] = orr;
            }
        }
    }
}

// launch 4: finalize offsets. Each block recomputes its own exclusive prefix
// of the block totals (<= 196 values) with a shared-mem reduction.
__global__ void scan3_kernel() {
    __shared__ int sh[SCAN_BLK];
    int tid = threadIdx.x;
    int bid = blockIdx.x;
    sh[tid] = (tid < bid) ? g_bsum[tid] : 0;        // bid <= 196 <= SCAN_BLK
    __syncthreads();
    #pragma unroll
    for (int o = SCAN_BLK / 2; o > 0; o >>= 1) {
        if (tid < o) sh[tid] += sh[tid + o];
        __syncthreads();
    }
    int prefix = sh[0];
    int i = bid * SCAN_BLK + tid;
    if (i < N_NODES) {
        int excl = g_off[i] - g_deg[i] + prefix;
        g_off[i] = excl;
        g_cursor[i] = excl;
    }
}

// launch 5: CSR fill
__global__ void fill_kernel(const void* __restrict__ ei_raw) {
    int is64 = g_is64;
    int i = blockIdx.x * blockDim.x + threadIdx.x;
    int stride = gridDim.x * blockDim.x;
    for (int e = i; e < N_EDGES; e += stride) {
        int s = load_idx(ei_raw, e, is64);
        int d = load_idx(ei_raw, N_EDGES + e, is64);
        int pos = atomicAdd(&g_cursor[d], 1);
        g_csr_src[pos] = s;
    }
}

// ---------------------------------------------------------------------------
// launch 6: fused per-dst softmax-gather + residual + LN.
// One warp per destination node; edge loop unrolled x4 with independent
// accumulator pairs (MLP=4). alpha = exp(e)/sum(exp(e)) equals reference
// softmax (max cancels; +1e-16 negligible since max term contributes 1).
// ---------------------------------------------------------------------------
__device__ __forceinline__ float edge_logit(float4 a, float4 xr4, float4 at) {
    float vx = a.x + xr4.x; vx = vx > 0.f ? vx : NEG_SLOPE * vx;
    float vy = a.y + xr4.y; vy = vy > 0.f ? vy : NEG_SLOPE * vy;
    float vz = a.z + xr4.z; vz = vz > 0.f ? vz : NEG_SLOPE * vz;
    float vw = a.w + xr4.w; vw = vw > 0.f ? vw : NEG_SLOPE * vw;
    return vx * at.x + vy * at.y + vz * at.z + vw * at.w;
}

__global__ void fused_edge_kernel(const float* __restrict__ x,
                                  const float* __restrict__ att,
                                  const float* __restrict__ bias,
                                  const float* __restrict__ gamma,
                                  const float* __restrict__ beta,
                                  float* __restrict__ out) {
    const int lane = threadIdx.x & 31;
    const int warp = (blockIdx.x * blockDim.x + threadIdx.x) >> 5;
    const int nwarp = (gridDim.x * blockDim.x) >> 5;
    const unsigned FULL = 0xffffffffu;

    float4 at = ((const float4*)att)[lane];
    float4 bi = ((const float4*)bias)[lane];
    float4 ga = ((const float4*)gamma)[lane];
    float4 be = ((const float4*)beta)[lane];

    for (int d = warp; d < N_NODES; d += nwarp) {
        const int beg = g_off[d];
        const int deg = g_deg[d];
        float4 xr4 = ((const float4*)(g_xr + (size_t)d * DIM))[lane];

        float4 accA = make_float4(0.f, 0.f, 0.f, 0.f);
        float4 accB = make_float4(0.f, 0.f, 0.f, 0.f);
        float denA = 0.f, denB = 0.f;

        for (int base = 0; base < deg; base += 32) {
            int cnt = min(32, deg - base);
            int my_src = (lane < cnt) ? g_csr_src[beg + base + lane] : 0;

            int j = 0;
            for (; j + 4 <= cnt; j += 4) {
                int s0 = __shfl_sync(FULL, my_src, j + 0);
                int s1 = __shfl_sync(FULL, my_src, j + 1);
                int s2 = __shfl_sync(FULL, my_src, j + 2);
                int s3 = __shfl_sync(FULL, my_src, j + 3);
                float4 a0 = ((const float4*)(g_xl + (size_t)s0 * DIM))[lane];
                float4 a1 = ((const float4*)(g_xl + (size_t)s1 * DIM))[lane];
                float4 a2 = ((const float4*)(g_xl + (size_t)s2 * DIM))[lane];
                float4 a3 = ((const float4*)(g_xl + (size_t)s3 * DIM))[lane];

                float p0 = edge_logit(a0, xr4, at);
                float p1 = edge_logit(a1, xr4, at);
                float p2 = edge_logit(a2, xr4, at);
                float p3 = edge_logit(a3, xr4, at);
                #pragma unroll
                for (int off = 4; off > 0; off >>= 1) {
                    p0 += __shfl_xor_sync(FULL, p0, off);
                    p1 += __shfl_xor_sync(FULL, p1, off);
                    p2 += __shfl_xor_sync(FULL, p2, off);
                    p3 += __shfl_xor_sync(FULL, p3, off);
                }
                float w0 = __expf(p0), w1 = __expf(p1);
                float w2 = __expf(p2), w3 = __expf(p3);
                denA += w0 + w1;
                denB += w2 + w3;
                accA.x += w0 * a0.x + w1 * a1.x;
                accA.y += w0 * a0.y + w1 * a1.y;
                accA.z += w0 * a0.z + w1 * a1.z;
                accA.w += w0 * a0.w + w1 * a1.w;
                accB.x += w2 * a2.x + w3 * a3.x;
                accB.y += w2 * a2.y + w3 * a3.y;
                accB.z += w2 * a2.z + w3 * a3.z;
                accB.w += w2 * a2.w + w3 * a3.w;
            }
            for (; j < cnt; j++) {
                int s = __shfl_sync(FULL, my_src, j);
                float4 a = ((const float4*)(g_xl + (size_t)s * DIM))[lane];
                float p = edge_logit(a, xr4, at);
                #pragma unroll
                for (int off = 4; off > 0; off >>= 1)
                    p += __shfl_xor_sync(FULL, p, off);
                float w = __expf(p);
                denA += w;
                accA.x += w * a.x;
                accA.y += w * a.y;
                accA.z += w * a.z;
                accA.w += w * a.w;
            }
        }

        float den = denA + denB;
        float4 acc = make_float4(accA.x + accB.x, accA.y + accB.y,
                                 accA.z + accB.z, accA.w + accB.w);
        float inv = (den > 0.f) ? __frcp_rn(den) : 0.f;

        float4 xv = ((const float4*)(x + (size_t)d * DIM))[lane];
        float4 o;
        o.x = acc.x * inv + bi.x + xv.x;
        o.y = acc.y * inv + bi.y + xv.y;
        o.z = acc.z * inv + bi.z + xv.z;
        o.w = acc.w * inv + bi.w + xv.w;

        float s = o.x + o.y + o.z + o.w;
        #pragma unroll
        for (int off = 16; off > 0; off >>= 1)
            s += __shfl_xor_sync(FULL, s, off);
        float mu = s * (1.0f / DIM);

        float dx = o.x - mu, dy = o.y - mu, dz = o.z - mu, dw = o.w - mu;
        float q = dx * dx + dy * dy + dz * dz + dw * dw;
        #pragma unroll
        for (int off = 16; off > 0; off >>= 1)
            q += __shfl_xor_sync(FULL, q, off);
        float rs = rsqrtf(q * (1.0f / DIM) + LN_EPS);

        float4 r;
        r.x = dx * rs * ga.x + be.x;
        r.y = dy * rs * ga.y + be.y;
        r.z = dz * rs * ga.z + be.z;
        r.w = dw * rs * ga.w + be.w;
        ((float4*)(out + (size_t)d * DIM))[lane] = r;
    }
}

extern "C" void kernel_launch(void* const* d_in, const int* in_sizes, int n_in,
                              void* d_out, int out_size) {
    const float* x     = (const float*)d_in[0];
    const void*  ei    = d_in[1];
    const float* Wl    = (const float*)d_in[2];
    const float* bl    = (const float*)d_in[3];
    const float* Wr    = (const float*)d_in[4];
    const float* br    = (const float*)d_in[5];
    const float* att   = (const float*)d_in[6];
    const float* bias  = (const float*)d_in[7];
    const float* gamma = (const float*)d_in[8];
    const float* beta  = (const float*)d_in[9];
    float*       out   = (float*)d_out;

    static int smem_set = 0;
    if (!smem_set) {
        cudaFuncSetAttribute(gemm_kernel,
                             cudaFuncAttributeMaxDynamicSharedMemorySize, GEMM_SMEM);
        smem_set = 1;
    }

    prep_kernel<<<256, 256>>>(ei);                          // 0
    hist_kernel<<<1024, 256>>>(ei);                         // 1
    scan1_kernel<<<N_SCAN_BLKS, SCAN_BLK>>>();              // 2
    // ceil(50000 / 64) = 782 blocks, 64 KB dynamic smem each
    gemm_kernel<<<782, 256, GEMM_SMEM>>>(x, Wl, bl, Wr, br);  // 3  <- ncu captures
    scan3_kernel<<<N_SCAN_BLKS, SCAN_BLK>>>();              // 4
    fill_kernel<<<1024, 256>>>(ei);                         // 5
    fused_edge_kernel<<<6250, 256>>>(x, att, bias, gamma, beta, out);  // 6
}

// round 11
// speedup vs baseline: 1.3132x; 1.1131x over previous
#include <cuda_runtime.h>

#define N_NODES 50000
#define N_EDGES 800000
#define DIM 128
#define HEADS 4
#define NEG_SLOPE 0.2f
#define LN_EPS 1e-5f

#define SCAN_BLK 256
#define N_SCAN_BLKS ((N_NODES + SCAN_BLK - 1) / SCAN_BLK)   // 196

// Scratch (device globals: no allocation allowed in kernel_launch)
__device__ __align__(16) float g_xl[N_NODES * DIM];   // 25.6 MB
__device__ __align__(16) float g_xr[N_NODES * DIM];   // 25.6 MB
__device__ int g_deg[N_NODES];
__device__ int g_off[N_NODES];
__device__ int g_cursor[N_NODES];
__device__ int g_bsum[N_SCAN_BLKS];
__device__ int g_csr_src[N_EDGES];
__device__ int g_is64;

__device__ __forceinline__ int load_idx(const void* raw, int pos, int is64) {
    return is64 ? (int)((const long long*)raw)[pos] : ((const int*)raw)[pos];
}

// f32x2 packed helpers (sm_103a FFMA2 — only reachable via PTX)
__device__ __forceinline__ unsigned long long pack_dup(float v) {
    unsigned long long r;
    asm("mov.b64 %0, {%1, %1};" : "=l"(r) : "f"(v));
    return r;
}
__device__ __forceinline__ void fma2(unsigned long long& acc,
                                     unsigned long long a, unsigned long long b) {
    asm("fma.rn.f32x2 %0, %1, %2, %0;" : "+l"(acc) : "l"(a), "l"(b));
}
__device__ __forceinline__ float2 unpack2(unsigned long long v) {
    float lo, hi;
    asm("mov.b64 {%0, %1}, %2;" : "=f"(lo), "=f"(hi) : "l"(v));
    return make_float2(lo, hi);
}

// ---------------------------------------------------------------------------
// CSR stream: dtype sniff + zero degree array.
// ---------------------------------------------------------------------------
__global__ void prep_kernel(const void* __restrict__ ei_raw) {
    int i = blockIdx.x * blockDim.x + threadIdx.x;
    if (i == 0) {
        const long long* e64 = (const long long*)ei_raw;
        int ok = 1;
        #pragma unroll
        for (int j = 0; j < 16; j++) {
            long long v = e64[j];
            if (v < 0 || v >= N_NODES) ok = 0;
        }
        g_is64 = ok;
    }
    int stride = gridDim.x * blockDim.x;
    for (int j = i; j < N_NODES; j += stride) g_deg[j] = 0;
}

// CSR stream: degree histogram
__global__ void hist_kernel(const void* __restrict__ ei_raw) {
    int is64 = g_is64;
    int i = blockIdx.x * blockDim.x + threadIdx.x;
    int stride = gridDim.x * blockDim.x;
    for (int e = i; e < N_EDGES; e += stride) {
        int d = load_idx(ei_raw, N_EDGES + e, is64);
        atomicAdd(&g_deg[d], 1);
    }
}

// CSR stream: per-block inclusive scan of deg chunk; block total to g_bsum.
__global__ void scan1_kernel() {
    __shared__ int sh[SCAN_BLK];
    int tid = threadIdx.x;
    int i = blockIdx.x * SCAN_BLK + tid;
    int v = (i < N_NODES) ? g_deg[i] : 0;
    sh[tid] = v;
    __syncthreads();
    #pragma unroll
    for (int o = 1; o < SCAN_BLK; o <<= 1) {
        int t = (tid >= o) ? sh[tid - o] : 0;
        __syncthreads();
        sh[tid] += t;
        __syncthreads();
    }
    if (i < N_NODES) g_off[i] = sh[tid];           // inclusive local
    if (tid == SCAN_BLK - 1) g_bsum[blockIdx.x] = sh[tid];
}

// CSR stream: finalize offsets (each block reduces its prefix of block totals)
__global__ void scan3_kernel() {
    __shared__ int sh[SCAN_BLK];
    int tid = threadIdx.x;
    int bid = blockIdx.x;
    sh[tid] = (tid < bid) ? g_bsum[tid] : 0;        // bid <= 196 <= SCAN_BLK
    __syncthreads();
    #pragma unroll
    for (int o = SCAN_BLK / 2; o > 0; o >>= 1) {
        if (tid < o) sh[tid] += sh[tid + o];
        __syncthreads();
    }
    int prefix = sh[0];
    int i = bid * SCAN_BLK + tid;
    if (i < N_NODES) {
        int excl = g_off[i] - g_deg[i] + prefix;
        g_off[i] = excl;
        g_cursor[i] = excl;
    }
}

// CSR stream: fill
__global__ void fill_kernel(const void* __restrict__ ei_raw) {
    int is64 = g_is64;
    int i = blockIdx.x * blockDim.x + threadIdx.x;
    int stride = gridDim.x * blockDim.x;
    for (int e = i; e < N_EDGES; e += stride) {
        int s = load_idx(ei_raw, e, is64);
        int d = load_idx(ei_raw, N_EDGES + e, is64);
        int pos = atomicAdd(&g_cursor[d], 1);
        g_csr_src[pos] = s;
    }
}

// ---------------------------------------------------------------------------
// GEMM stream: xl = x@W_l + b_l ; xr = x@W_r + b_r (R7 version, best scalar).
// Warp computes 4 nodes; lane L owns output columns [4L, 4L+4) of both
// matrices. Packed fma.rn.f32x2 inner loop (bit-exact fp32 per half).
// ---------------------------------------------------------------------------
__global__ void __launch_bounds__(256, 2)
gemm_kernel(const float* __restrict__ x,
            const float* __restrict__ Wl, const float* __restrict__ bl,
            const float* __restrict__ Wr, const float* __restrict__ br) {
    const int lane = threadIdx.x & 31;
    const int warp = (blockIdx.x * blockDim.x + threadIdx.x) >> 5;
    const int nwarp = (gridDim.x * blockDim.x) >> 5;
    const int NPW = 4;

    float4 bl4 = ((const float4*)bl)[lane];
    float4 br4 = ((const float4*)br)[lane];

    for (int base = warp * NPW; base < N_NODES; base += nwarp * NPW) {
        float4 xv[NPW];
        #pragma unroll
        for (int i = 0; i < NPW; i++) {
            int n = base + i;
            xv[i] = (n < N_NODES) ? ((const float4*)(x + (size_t)n * DIM))[lane]
                                  : make_float4(0.f, 0.f, 0.f, 0.f);
        }
        unsigned long long al2[NPW][2], ar2[NPW][2];
        #pragma unroll
        for (int i = 0; i < NPW; i++) {
            al2[i][0] = 0ull; al2[i][1] = 0ull;
            ar2[i][0] = 0ull; ar2[i][1] = 0ull;
        }

        #pragma unroll
        for (int k4 = 0; k4 < DIM / 4; k4++) {
            #pragma unroll
            for (int c = 0; c < 4; c++) {
                const int k = k4 * 4 + c;
                ulonglong2 wl2 = ((const ulonglong2*)(Wl + (size_t)k * DIM))[lane];
                ulonglong2 wr2 = ((const ulonglong2*)(Wr + (size_t)k * DIM))[lane];
                #pragma unroll
                for (int i = 0; i < NPW; i++) {
                    float comp = (c == 0) ? xv[i].x : (c == 1) ? xv[i].y
                               : (c == 2) ? xv[i].z : xv[i].w;
                    float xk = __shfl_sync(0xffffffffu, comp, k4);
                    unsigned long long xk2 = pack_dup(xk);
                    fma2(al2[i][0], wl2.x, xk2);
                    fma2(al2[i][1], wl2.y, xk2);
                    fma2(ar2[i][0], wr2.x, xk2);
                    fma2(ar2[i][1], wr2.y, xk2);
                }
            }
        }

        #pragma unroll
        for (int i = 0; i < NPW; i++) {
            int n = base + i;
            if (n < N_NODES) {
                float2 l01 = unpack2(al2[i][0]);
                float2 l23 = unpack2(al2[i][1]);
                float2 r01 = unpack2(ar2[i][0]);
                float2 r23 = unpack2(ar2[i][1]);
                float4 ol = make_float4(l01.x + bl4.x, l01.y + bl4.y,
                                        l23.x + bl4.z, l23.y + bl4.w);
                float4 orr = make_float4(r01.x + br4.x, r01.y + br4.y,
                                         r23.x + br4.z, r23.y + br4.w);
                ((float4*)(g_xl + (size_t)n * DIM))[lane] = ol;
                ((float4*)(g_xr + (size_t)n * DIM))[lane] = orr;
            }
        }
    }
}

// ---------------------------------------------------------------------------
// join: fused per-dst softmax-gather + residual + LN.
// One warp per destination node; edge loop unrolled x4 with independent
// accumulator pairs (MLP=4). alpha = exp(e)/sum(exp(e)) equals reference
// softmax (max cancels; +1e-16 negligible since max term contributes 1).
// ---------------------------------------------------------------------------
__device__ __forceinline__ float edge_logit(float4 a, float4 xr4, float4 at) {
    float vx = a.x + xr4.x; vx = vx > 0.f ? vx : NEG_SLOPE * vx;
    float vy = a.y + xr4.y; vy = vy > 0.f ? vy : NEG_SLOPE * vy;
    float vz = a.z + xr4.z; vz = vz > 0.f ? vz : NEG_SLOPE * vz;
    float vw = a.w + xr4.w; vw = vw > 0.f ? vw : NEG_SLOPE * vw;
    return vx * at.x + vy * at.y + vz * at.z + vw * at.w;
}

__global__ void fused_edge_kernel(const float* __restrict__ x,
                                  const float* __restrict__ att,
                                  const float* __restrict__ bias,
                                  const float* __restrict__ gamma,
                                  const float* __restrict__ beta,
                                  float* __restrict__ out) {
    const int lane = threadIdx.x & 31;
    const int warp = (blockIdx.x * blockDim.x + threadIdx.x) >> 5;
    const int nwarp = (gridDim.x * blockDim.x) >> 5;
    const unsigned FULL = 0xffffffffu;

    float4 at = ((const float4*)att)[lane];
    float4 bi = ((const float4*)bias)[lane];
    float4 ga = ((const float4*)gamma)[lane];
    float4 be = ((const float4*)beta)[lane];

    for (int d = warp; d < N_NODES; d += nwarp) {
        const int beg = g_off[d];
        const int deg = g_deg[d];
        float4 xr4 = ((const float4*)(g_xr + (size_t)d * DIM))[lane];

        float4 accA = make_float4(0.f, 0.f, 0.f, 0.f);
        float4 accB = make_float4(0.f, 0.f, 0.f, 0.f);
        float denA = 0.f, denB = 0.f;

        for (int base = 0; base < deg; base += 32) {
            int cnt = min(32, deg - base);
            int my_src = (lane < cnt) ? g_csr_src[beg + base + lane] : 0;

            int j = 0;
            for (; j + 4 <= cnt; j += 4) {
                int s0 = __shfl_sync(FULL, my_src, j + 0);
                int s1 = __shfl_sync(FULL, my_src, j + 1);
                int s2 = __shfl_sync(FULL, my_src, j + 2);
                int s3 = __shfl_sync(FULL, my_src, j + 3);
                float4 a0 = ((const float4*)(g_xl + (size_t)s0 * DIM))[lane];
                float4 a1 = ((const float4*)(g_xl + (size_t)s1 * DIM))[lane];
                float4 a2 = ((const float4*)(g_xl + (size_t)s2 * DIM))[lane];
                float4 a3 = ((const float4*)(g_xl + (size_t)s3 * DIM))[lane];

                float p0 = edge_logit(a0, xr4, at);
                float p1 = edge_logit(a1, xr4, at);
                float p2 = edge_logit(a2, xr4, at);
                float p3 = edge_logit(a3, xr4, at);
                #pragma unroll
                for (int off = 4; off > 0; off >>= 1) {
                    p0 += __shfl_xor_sync(FULL, p0, off);
                    p1 += __shfl_xor_sync(FULL, p1, off);
                    p2 += __shfl_xor_sync(FULL, p2, off);
                    p3 += __shfl_xor_sync(FULL, p3, off);
                }
                float w0 = __expf(p0), w1 = __expf(p1);
                float w2 = __expf(p2), w3 = __expf(p3);
                denA += w0 + w1;
                denB += w2 + w3;
                accA.x += w0 * a0.x + w1 * a1.x;
                accA.y += w0 * a0.y + w1 * a1.y;
                accA.z += w0 * a0.z + w1 * a1.z;
                accA.w += w0 * a0.w + w1 * a1.w;
                accB.x += w2 * a2.x + w3 * a3.x;
                accB.y += w2 * a2.y + w3 * a3.y;
                accB.z += w2 * a2.z + w3 * a3.z;
                accB.w += w2 * a2.w + w3 * a3.w;
            }
            for (; j < cnt; j++) {
                int s = __shfl_sync(FULL, my_src, j);
                float4 a = ((const float4*)(g_xl + (size_t)s * DIM))[lane];
                float p = edge_logit(a, xr4, at);
                #pragma unroll
                for (int off = 4; off > 0; off >>= 1)
                    p += __shfl_xor_sync(FULL, p, off);
                float w = __expf(p);
                denA += w;
                accA.x += w * a.x;
                accA.y += w * a.y;
                accA.z += w * a.z;
                accA.w += w * a.w;
            }
        }

        float den = denA + denB;
        float4 acc = make_float4(accA.x + accB.x, accA.y + accB.y,
                                 accA.z + accB.z, accA.w + accB.w);
        float inv = (den > 0.f) ? __frcp_rn(den) : 0.f;

        float4 xv = ((const float4*)(x + (size_t)d * DIM))[lane];
        float4 o;
        o.x = acc.x * inv + bi.x + xv.x;
        o.y = acc.y * inv + bi.y + xv.y;
        o.z = acc.z * inv + bi.z + xv.z;
        o.w = acc.w * inv + bi.w + xv.w;

        float s = o.x + o.y + o.z + o.w;
        #pragma unroll
        for (int off = 16; off > 0; off >>= 1)
            s += __shfl_xor_sync(FULL, s, off);
        float mu = s * (1.0f / DIM);

        float dx = o.x - mu, dy = o.y - mu, dz = o.z - mu, dw = o.w - mu;
        float q = dx * dx + dy * dy + dz * dz + dw * dw;
        #pragma unroll
        for (int off = 16; off > 0; off >>= 1)
            q += __shfl_xor_sync(FULL, q, off);
        float rs = rsqrtf(q * (1.0f / DIM) + LN_EPS);

        float4 r;
        r.x = dx * rs * ga.x + be.x;
        r.y = dy * rs * ga.y + be.y;
        r.z = dz * rs * ga.z + be.z;
        r.w = dw * rs * ga.w + be.w;
        ((float4*)(out + (size_t)d * DIM))[lane] = r;
    }
}

extern "C" void kernel_launch(void* const* d_in, const int* in_sizes, int n_in,
                              void* d_out, int out_size) {
    const float* x     = (const float*)d_in[0];
    const void*  ei    = d_in[1];
    const float* Wl    = (const float*)d_in[2];
    const float* bl    = (const float*)d_in[3];
    const float* Wr    = (const float*)d_in[4];
    const float* br    = (const float*)d_in[5];
    const float* att   = (const float*)d_in[6];
    const float* bias  = (const float*)d_in[7];
    const float* gamma = (const float*)d_in[8];
    const float* beta  = (const float*)d_in[9];
    float*       out   = (float*)d_out;

    // Lazily-created side streams/events (host handles only; no device mem).
    static cudaStream_t s_gemm = nullptr, s_csr = nullptr;
    static cudaEvent_t ev_fork = nullptr, ev_gemm = nullptr, ev_csr = nullptr;
    if (!s_gemm) {
        cudaStreamCreateWithFlags(&s_gemm, cudaStreamNonBlocking);
        cudaStreamCreateWithFlags(&s_csr, cudaStreamNonBlocking);
        cudaEventCreateWithFlags(&ev_fork, cudaEventDisableTiming);
        cudaEventCreateWithFlags(&ev_gemm, cudaEventDisableTiming);
        cudaEventCreateWithFlags(&ev_csr, cudaEventDisableTiming);
    }

    // Fork from the default stream (capture-safe event fork/join pattern).
    cudaEventRecord(ev_fork, 0);
    cudaStreamWaitEvent(s_gemm, ev_fork, 0);
    cudaStreamWaitEvent(s_csr, ev_fork, 0);

    // GEMM branch (independent of CSR build): ~90 us
    gemm_kernel<<<1563, 256, 0, s_gemm>>>(x, Wl, bl, Wr, br);

    // CSR branch: ~40 us, runs concurrently with the GEMM
    prep_kernel<<<256, 256, 0, s_csr>>>(ei);
    hist_kernel<<<1024, 256, 0, s_csr>>>(ei);
    scan1_kernel<<<N_SCAN_BLKS, SCAN_BLK, 0, s_csr>>>();
    scan3_kernel<<<N_SCAN_BLKS, SCAN_BLK, 0, s_csr>>>();
    fill_kernel<<<1024, 256, 0, s_csr>>>(ei);

    // Join both branches back onto the default stream.
    cudaEventRecord(ev_gemm, s_gemm);
    cudaEventRecord(ev_csr, s_csr);
    cudaStreamWaitEvent(0, ev_gemm, 0);
    cudaStreamWaitEvent(0, ev_csr, 0);

    fused_edge_kernel<<<6250, 256>>>(x, att, bias, gamma, beta, out);
}